// round 16
// baseline (speedup 1.0000x reference)
#include <cuda_runtime.h>
#include <cuda_fp16.h>
#include <cstdint>

// GATConv_74904229642448 — attention collapses to multiply-by-one (row-
// normalized alpha contracted only over its normalization axis):
//   out[n, j] = dot(x[n,:], W[(j&7)*64 + (j>>3), :]) + bias[j]
// => 4096x512x256 fp32 GEMM, adj unused.
//
// Single-term fp16 mma.sync GEMM (rel_err 2.8e-4, gate 1e-3). R16: the
// kernel is latency-bound (tensor pipe only needs 3.2k cyc; R15 ran 19.5k
// with occ 25%). Shrink tile to 128x64 / 99 KB smem => 2 CTAs per SM,
// 32 warps/SM: cross-CTA overlap fills the load/ldm/MMA latency gaps.

#define N_NODES 4096
#define IN_C    256
#define OUT_TOT 512
#define BM 128
#define BN 64
#define PITCH 528                  // 256 fp16 * 2B + 16B pad (conflict-free ldm)
#define REGX (128u * PITCH)        // 67584 B  (X tile)
#define REGW (64u * PITCH)         // 33792 B  (W tile)
#define SMEMB (REGX + REGW)        // 101376 B -> 2 CTAs/SM

#define XT (N_NODES * IN_C)
#define WT (OUT_TOT * IN_C)

__device__ __align__(16) __half g_xh[XT];
__device__ __align__(16) __half g_wh[WT];

static __device__ __forceinline__ uint32_t smem_u32(const void* p) {
    uint32_t a;
    asm("{ .reg .u64 t; cvta.to.shared.u64 t, %1; cvt.u32.u64 %0, t; }"
        : "=r"(a) : "l"(p));
    return a;
}

static __device__ __forceinline__ uint32_t packh(__half a, __half b) {
    return ((uint32_t)__half_as_ushort(b) << 16) | (uint32_t)__half_as_ushort(a);
}

// ---------------- pre-pass: x, W(permuted) -> fp16 ----------------
__global__ __launch_bounds__(256, 8)
void cvt_pre(const float* __restrict__ x, const float* __restrict__ W)
{
    const int i = blockIdx.x * 256 + threadIdx.x;   // one float4 per thread
    if (i < XT / 4) {
        const float4 v = ((const float4*)x)[i];
        *(uint2*)(g_xh + i * 4) =
            make_uint2(packh(__float2half_rn(v.x), __float2half_rn(v.y)),
                       packh(__float2half_rn(v.z), __float2half_rn(v.w)));
    } else {
        const int j = i - XT / 4;                   // < WT/4
        const int row = j >> 6;                     // permuted (output) row
        const int srow = (row & 7) * 64 + (row >> 3);
        const float4 v = ((const float4*)W)[srow * 64 + (j & 63)];
        *(uint2*)(g_wh + j * 4) =
            make_uint2(packh(__float2half_rn(v.x), __float2half_rn(v.y)),
                       packh(__float2half_rn(v.z), __float2half_rn(v.w)));
    }
}

// ---------------- GEMM ----------------
static __device__ __forceinline__ void cp16(uint32_t dst, const __half* src) {
    asm volatile("cp.async.cg.shared.global [%0], [%1], 16;"
                 :: "r"(dst), "l"(src) : "memory");
}

static __device__ __forceinline__ void ldm4(uint32_t d[4], uint32_t addr) {
    asm volatile("ldmatrix.sync.aligned.m8n8.x4.shared.b16 {%0,%1,%2,%3}, [%4];"
                 : "=r"(d[0]), "=r"(d[1]), "=r"(d[2]), "=r"(d[3]) : "r"(addr));
}

static __device__ __forceinline__ void mma16816(float c[4], const uint32_t a[4],
                                                uint32_t b0, uint32_t b1) {
    asm volatile(
        "mma.sync.aligned.m16n8k16.row.col.f32.f16.f16.f32 "
        "{%0,%1,%2,%3}, {%4,%5,%6,%7}, {%8,%9}, {%0,%1,%2,%3};"
        : "+f"(c[0]), "+f"(c[1]), "+f"(c[2]), "+f"(c[3])
        : "r"(a[0]), "r"(a[1]), "r"(a[2]), "r"(a[3]), "r"(b0), "r"(b1));
}

extern __shared__ __align__(16) unsigned char dynsmem[];

__global__ __launch_bounds__(512, 2)
void gat_mma8(const float* __restrict__ bias, float* __restrict__ out)
{
    const uint32_t S = smem_u32(dynsmem);
    const uint32_t XH = S;
    const uint32_t WH = S + REGX;

    const int tid  = threadIdx.x;
    const int lane = tid & 31;
    const int warp = tid >> 5;          // 0..15
    const int wm = (warp >> 2) * 32;    // 4 warp-rows of 32
    const int wn = (warp & 3) * 16;     // 4 warp-cols of 16
    const int m0 = blockIdx.y * BM;
    const int n0 = blockIdx.x * BN;

    // Load volley: X tile 128x32segs (8 per thread), W tile 64x32segs (4/thr).
    {
        const int rx  = tid >> 2;             // 0..127
        const int sx  = tid & 3;
        const __half* px = g_xh + (size_t)(m0 + rx) * IN_C + sx * 8;
        const uint32_t dx = XH + (uint32_t)(rx * PITCH + sx * 16);
        #pragma unroll
        for (int s = 0; s < 8; s++)
            cp16(dx + s * 64u, px + s * 32);

        const int rw  = tid >> 3;             // 0..63
        const int sw  = tid & 7;
        const __half* pw = g_wh + (size_t)(n0 + rw) * IN_C + sw * 8;
        const uint32_t dw = WH + (uint32_t)(rw * PITCH + sw * 16);
        #pragma unroll
        for (int s = 0; s < 4; s++)
            cp16(dw + s * 128u, pw + s * 64);

        asm volatile("cp.async.commit_group;" ::: "memory");
    }

    float acc[2][2][4];
    #pragma unroll
    for (int t = 0; t < 2; t++)
        #pragma unroll
        for (int u = 0; u < 2; u++)
            #pragma unroll
            for (int e = 0; e < 4; e++)
                acc[t][u][e] = 0.f;

    asm volatile("cp.async.wait_group 0;" ::: "memory");
    __syncthreads();                       // the ONLY barrier before epilogue

    // 16 k-steps, no synchronization: 3 ldm4 + 4 MMA each.
    #pragma unroll
    for (int kk = 0; kk < 16; kk++) {
        uint32_t ah[2][4], bh[4];
        #pragma unroll
        for (int t = 0; t < 2; t++) {
            uint32_t off = (uint32_t)((wm + t * 16 + (lane & 15)) * PITCH
                                      + kk * 32 + ((lane >> 4) << 4));
            ldm4(ah[t], XH + off);
        }
        {
            uint32_t off = (uint32_t)((wn + ((lane >> 4) << 3) + (lane & 7)) * PITCH
                                      + kk * 32 + ((lane >> 3) & 1) * 16);
            ldm4(bh, WH + off);
        }
        #pragma unroll
        for (int t = 0; t < 2; t++)
            #pragma unroll
            for (int u = 0; u < 2; u++)
                mma16816(acc[t][u], ah[t], bh[u * 2], bh[u * 2 + 1]);
    }

    // Epilogue: bias + store. m16n8 acc mapping:
    //   c0:(row=lane>>2, col=(lane&3)*2) c1:col+1 c2:row+8 c3:row+8,col+1
    #pragma unroll
    for (int u = 0; u < 2; u++) {
        const int col = n0 + wn + u * 8 + (lane & 3) * 2;
        const float2 bv = *(const float2*)(bias + col);
        #pragma unroll
        for (int t = 0; t < 2; t++) {
            const int row = m0 + wm + t * 16 + (lane >> 2);
            float2 o0 = make_float2(acc[t][u][0] + bv.x, acc[t][u][1] + bv.y);
            float2 o1 = make_float2(acc[t][u][2] + bv.x, acc[t][u][3] + bv.y);
            *(float2*)(out + (size_t)row * OUT_TOT + col) = o0;
            *(float2*)(out + (size_t)(row + 8) * OUT_TOT + col) = o1;
        }
    }
}

extern "C" void kernel_launch(void* const* d_in, const int* in_sizes, int n_in,
                              void* d_out, int out_size) {
    // metadata order: adj, x, W, att_src, att_dst, bias
    const float* x    = (const float*)d_in[1];
    const float* W    = (const float*)d_in[2];
    const float* bias = (const float*)d_in[5];
    float* out        = (float*)d_out;

    cudaFuncSetAttribute(gat_mma8, cudaFuncAttributeMaxDynamicSharedMemorySize,
                         (int)SMEMB);

    const int pre_blocks = (XT / 4 + WT / 4) / 256;      // 1152
    cvt_pre<<<pre_blocks, 256>>>(x, W);

    dim3 grid(OUT_TOT / BN, N_NODES / BM);               // (8, 32) = 256 CTAs
    gat_mma8<<<grid, 512, SMEMB>>>(bias, out);
}

// round 17
// speedup vs baseline: 1.3851x; 1.3851x over previous
#include <cuda_runtime.h>
#include <cuda_fp16.h>
#include <cstdint>

// GATConv_74904229642448 — attention collapses to multiply-by-one (row-
// normalized alpha contracted only over its normalization axis):
//   out[n, j] = dot(x[n,:], W[(j&7)*64 + (j>>3), :]) + bias[j]
// => 4096x512x256 fp32 GEMM, adj unused.
//
// Single-term fp16 mma.sync GEMM (rel_err 2.8e-4, gate 1e-3). R17:
//  - fused: ONE kernel; each CTA converts its fp32 operands to fp16 in the
//    prologue (kills the prepass kernel + launch, -2.5us)
//  - ILP over TLP: 8 warps, warp tile 64x32 => 16 independent MMAs per
//    6 ldm4, explicit double-buffered fragments (reg headroom: 256 thr)
//  - single-shot smem (135 KB), ONE barrier, no k-loop chunking.

#define N_NODES 4096
#define IN_C    256
#define OUT_TOT 512
#define BM 128
#define BN 128
#define PITCH 528                  // 256 fp16 * 2B + 16B pad (conflict-free ldm)
#define REGION (128u * PITCH)      // 67584 B per operand tile
#define SMEMB (2u * REGION)        // 135168 B -> 1 CTA/SM

static __device__ __forceinline__ uint32_t smem_u32(const void* p) {
    uint32_t a;
    asm("{ .reg .u64 t; cvta.to.shared.u64 t, %1; cvt.u32.u64 %0, t; }"
        : "=r"(a) : "l"(p));
    return a;
}

static __device__ __forceinline__ void ldm4(uint32_t d[4], uint32_t addr) {
    asm volatile("ldmatrix.sync.aligned.m8n8.x4.shared.b16 {%0,%1,%2,%3}, [%4];"
                 : "=r"(d[0]), "=r"(d[1]), "=r"(d[2]), "=r"(d[3]) : "r"(addr));
}

static __device__ __forceinline__ void mma16816(float c[4], const uint32_t a[4],
                                                uint32_t b0, uint32_t b1) {
    asm volatile(
        "mma.sync.aligned.m16n8k16.row.col.f32.f16.f16.f32 "
        "{%0,%1,%2,%3}, {%4,%5,%6,%7}, {%8,%9}, {%0,%1,%2,%3};"
        : "+f"(c[0]), "+f"(c[1]), "+f"(c[2]), "+f"(c[3])
        : "r"(a[0]), "r"(a[1]), "r"(a[2]), "r"(a[3]), "r"(b0), "r"(b1));
}

static __device__ __forceinline__ uint32_t cvt2h(float a, float b) {
    __half2 h = __float22half2_rn(make_float2(a, b));
    return *(uint32_t*)&h;
}

extern __shared__ __align__(16) unsigned char dynsmem[];

__global__ __launch_bounds__(256, 1)
void gat_fused(const float* __restrict__ x,
               const float* __restrict__ W,
               const float* __restrict__ bias,
               float* __restrict__ out)
{
    const uint32_t S  = smem_u32(dynsmem);
    const uint32_t XH = S;
    const uint32_t WH = S + REGION;

    const int tid  = threadIdx.x;
    const int lane = tid & 31;
    const int warp = tid >> 5;          // 0..7
    const int wm = (warp >> 2) * 64;    // 2 warp-rows of 64
    const int wn = (warp & 3) * 32;     // 4 warp-cols of 32
    const int m0 = blockIdx.y * BM;
    const int n0 = blockIdx.x * BN;

    // ---- fused prologue: fp32 -> fp16 conversion into smem ----
    // X tile: 128 rows x 64 float4; 32 float4 per thread, coalesced.
    #pragma unroll
    for (int it = 0; it < 32; it++) {
        const int idx = tid + it * 256;         // 0..8191
        const int row = idx >> 6;
        const int c4  = idx & 63;
        const float4 v = *((const float4*)(x + (size_t)(m0 + row) * IN_C) + c4);
        *(uint2*)(dynsmem + row * PITCH + c4 * 8) =
            make_uint2(cvt2h(v.x, v.y), cvt2h(v.z, v.w));
    }
    // W tile (permuted rows): 128 rows x 64 float4.
    #pragma unroll
    for (int it = 0; it < 32; it++) {
        const int idx = tid + it * 256;
        const int row = idx >> 6;
        const int c4  = idx & 63;
        const int j = n0 + row;
        const int srow = (j & 7) * 64 + (j >> 3);
        const float4 v = *((const float4*)W + srow * 64 + c4);
        *(uint2*)(dynsmem + REGION + row * PITCH + c4 * 8) =
            make_uint2(cvt2h(v.x, v.y), cvt2h(v.z, v.w));
    }

    float acc[4][4][4];
    #pragma unroll
    for (int t = 0; t < 4; t++)
        #pragma unroll
        for (int u = 0; u < 4; u++)
            #pragma unroll
            for (int e = 0; e < 4; e++)
                acc[t][u][e] = 0.f;

    __syncthreads();                    // the ONLY barrier before epilogue

    // ---- main loop: 16 k-steps, double-buffered fragments ----
    uint32_t ah[2][4][4], bh[2][2][4];

    auto ldfrag = [&](int pb, int kk) {
        #pragma unroll
        for (int t = 0; t < 4; t++) {
            uint32_t off = (uint32_t)((wm + t * 16 + (lane & 15)) * PITCH
                                      + kk * 32 + ((lane >> 4) << 4));
            ldm4(ah[pb][t], XH + off);
        }
        #pragma unroll
        for (int u2 = 0; u2 < 2; u2++) {
            uint32_t off = (uint32_t)((wn + u2 * 16 + ((lane >> 4) << 3) + (lane & 7)) * PITCH
                                      + kk * 32 + ((lane >> 3) & 1) * 16);
            ldm4(bh[pb][u2], WH + off);
        }
    };

    ldfrag(0, 0);

    #pragma unroll
    for (int kk = 0; kk < 16; kk++) {
        const int pb = kk & 1;
        if (kk + 1 < 16) ldfrag(pb ^ 1, kk + 1);
        #pragma unroll
        for (int t = 0; t < 4; t++)
            #pragma unroll
            for (int u = 0; u < 4; u++) {
                const int u2 = u >> 1, e = (u & 1) * 2;
                mma16816(acc[t][u], ah[pb][t], bh[pb][u2][e], bh[pb][u2][e + 1]);
            }
    }

    // ---- epilogue: bias + store ----
    //   c0:(row=lane>>2, col=(lane&3)*2) c1:col+1 c2:row+8 c3:row+8,col+1
    #pragma unroll
    for (int u = 0; u < 4; u++) {
        const int col = n0 + wn + u * 8 + (lane & 3) * 2;
        const float2 bv = *(const float2*)(bias + col);
        #pragma unroll
        for (int t = 0; t < 4; t++) {
            const int row = m0 + wm + t * 16 + (lane >> 2);
            float2 o0 = make_float2(acc[t][u][0] + bv.x, acc[t][u][1] + bv.y);
            float2 o1 = make_float2(acc[t][u][2] + bv.x, acc[t][u][3] + bv.y);
            *(float2*)(out + (size_t)row * OUT_TOT + col) = o0;
            *(float2*)(out + (size_t)(row + 8) * OUT_TOT + col) = o1;
        }
    }
}

extern "C" void kernel_launch(void* const* d_in, const int* in_sizes, int n_in,
                              void* d_out, int out_size) {
    // metadata order: adj, x, W, att_src, att_dst, bias
    const float* x    = (const float*)d_in[1];
    const float* W    = (const float*)d_in[2];
    const float* bias = (const float*)d_in[5];
    float* out        = (float*)d_out;

    cudaFuncSetAttribute(gat_fused, cudaFuncAttributeMaxDynamicSharedMemorySize,
                         (int)SMEMB);

    dim3 grid(OUT_TOT / BN, N_NODES / BM);   // (4, 32) = 128 CTAs, one wave
    gat_fused<<<grid, 256, SMEMB>>>(x, W, bias, out);
}